// round 7
// baseline (speedup 1.0000x reference)
#include <cuda_runtime.h>
#include <cuda_fp16.h>
#include <stdint.h>

// NeuralODE RK4, fp16 mma (m16n8k16, fp32 accum), sm_103a.
// 64 CTAs x 256 threads (8 warps); CTA owns 16 batch rows, 127 steps.
// R7: fragment-major activation buffers (1 LDS.128 per A-quad, 2 STS.128 per
// stage write), paired-kt W1 SMEM layout (LDS.128 B loads), cross-barrier W1
// prefetch. W2 persistent in registers; tanh.approx epilogue.

#define ZDIM 256
#define TLEN 128
#define MROW 16
#define NCTA 64
#define WREC (16 * 32 * 32)       // uint2 records per matrix in WfG

#define OFF_W1  0                 // paired-kt W1 fragments: 8192 uint4 = 128 KB
#define OFF_AF  131072            // A fragment buffer: 512 uint4 = 8 KB
#define OFF_HF  139264            // H fragment buffer: 8 KB
#define SMEM_TOT 147456

__device__ uint2 WfG[2 * WREC];   // fragment-layout fp16 weights (prep output)

// ---- prep: W[k][n] row-major fp32 -> fp16 B-fragment layout ----
__global__ void prep_kernel(const float* __restrict__ W1, const float* __restrict__ W2)
{
    int idx = blockIdx.x * blockDim.x + threadIdx.x;
    if (idx >= 2 * WREC) return;
    int lane = idx & 31;
    int nt   = (idx >> 5) & 31;
    int kt   = (idx >> 10) & 15;
    int g    = idx >> 14;
    const float* W = g ? W2 : W1;
    int k0 = kt * 16 + 2 * (lane & 3);
    int n  = nt * 8 + (lane >> 2);
    __half2 lo = __floats2half2_rn(W[k0 * ZDIM + n],       W[(k0 + 1) * ZDIM + n]);
    __half2 hi = __floats2half2_rn(W[(k0 + 8) * ZDIM + n], W[(k0 + 9) * ZDIM + n]);
    uint2 v;
    v.x = *reinterpret_cast<unsigned*>(&lo);
    v.y = *reinterpret_cast<unsigned*>(&hi);
    WfG[idx] = v;
}

#define MMA16(ACC, A0, A1, A2, A3, BX, BY) \
    asm volatile("mma.sync.aligned.m16n8k16.row.col.f32.f16.f16.f32 " \
                 "{%0,%1,%2,%3}, {%4,%5,%6,%7}, {%8,%9}, {%0,%1,%2,%3};" \
                 : "+f"(ACC[0]), "+f"(ACC[1]), "+f"(ACC[2]), "+f"(ACC[3]) \
                 : "r"(A0), "r"(A1), "r"(A2), "r"(A3), "r"(BX), "r"(BY))

__device__ __forceinline__ float fast_tanh(float x) {
    float y; asm("tanh.approx.f32 %0, %1;" : "=f"(y) : "f"(x)); return y;
}
__device__ __forceinline__ unsigned pack2(float a, float b) {
    __half2 h = __floats2half2_rn(a, b);
    return *reinterpret_cast<unsigned*>(&h);
}

// GEMM1: A quads from fragment-major SMEM, B (W1) paired-kt LDS.128.
// bw[] preloaded with kt2=0 fragments before the barrier.
__device__ __forceinline__ void gemm_w1(const uint4* __restrict__ AfU4,
                                        const uint4* __restrict__ w1p,
                                        uint4 bw[4],
                                        int lane, int nt0, int aidx,
                                        const float bias[4][2], float acc[4][4])
{
#pragma unroll
    for (int t = 0; t < 4; t++) {
        acc[t][0] = bias[t][0]; acc[t][1] = bias[t][1];
        acc[t][2] = bias[t][0]; acc[t][3] = bias[t][1];
    }
#pragma unroll
    for (int kt2 = 0; kt2 < 8; kt2++) {
        uint4 av0 = AfU4[kt2 * 64 + aidx];
        uint4 av1 = AfU4[kt2 * 64 + 32 + aidx];
        uint4 bn[4];
        if (kt2 < 7) {
#pragma unroll
            for (int t = 0; t < 4; t++)
                bn[t] = w1p[((kt2 + 1) * 32 + nt0 + t) * 32 + lane];
        }
#pragma unroll
        for (int t = 0; t < 4; t++)
            MMA16(acc[t], av0.x, av0.y, av0.z, av0.w, bw[t].x, bw[t].y);
#pragma unroll
        for (int t = 0; t < 4; t++)
            MMA16(acc[t], av1.x, av1.y, av1.z, av1.w, bw[t].z, bw[t].w);
        if (kt2 < 7) {
#pragma unroll
            for (int t = 0; t < 4; t++) bw[t] = bn[t];
        }
    }
}

// GEMM2: A quads from fragment-major SMEM, B (W2) from persistent registers.
__device__ __forceinline__ void gemm_w2(const uint4* __restrict__ HfU4,
                                        const uint2 w2r[16][4],
                                        int aidx,
                                        const float bias[4][2], float acc[4][4])
{
#pragma unroll
    for (int t = 0; t < 4; t++) {
        acc[t][0] = bias[t][0]; acc[t][1] = bias[t][1];
        acc[t][2] = bias[t][0]; acc[t][3] = bias[t][1];
    }
#pragma unroll
    for (int kt2 = 0; kt2 < 8; kt2++) {
        uint4 av0 = HfU4[kt2 * 64 + aidx];
        uint4 av1 = HfU4[kt2 * 64 + 32 + aidx];
#pragma unroll
        for (int t = 0; t < 4; t++)
            MMA16(acc[t], av0.x, av0.y, av0.z, av0.w,
                  w2r[2 * kt2][t].x, w2r[2 * kt2][t].y);
#pragma unroll
        for (int t = 0; t < 4; t++)
            MMA16(acc[t], av1.x, av1.y, av1.z, av1.w,
                  w2r[2 * kt2 + 1][t].x, w2r[2 * kt2 + 1][t].y);
    }
}

__global__ void __launch_bounds__(256, 1)
node_kernel(const float* __restrict__ z0, const float* __restrict__ tg,
            const float* __restrict__ b1, const float* __restrict__ b2,
            float* __restrict__ out)
{
    extern __shared__ unsigned char smem_raw[];
    uint4* w1p  = reinterpret_cast<uint4*>(smem_raw + OFF_W1);
    uint4* AfU4 = reinterpret_cast<uint4*>(smem_raw + OFF_AF);
    uint4* HfU4 = reinterpret_cast<uint4*>(smem_raw + OFF_HF);

    const int tid  = threadIdx.x;
    const int lane = tid & 31;
    const int wid  = tid >> 5;           // 0..7
    const int nt0  = wid * 4;            // 4 n-tiles per warp
    const int r0   = lane >> 2;
    const int c0   = lane & 3;
    const int row0 = blockIdx.x * MROW;
    const int aidx = r0 * 4 + c0;        // A-quad index within a kt slab

    // Stage-write slots: values for t=0,1 go to kt=2*wid; t=2,3 to kt=2*wid+1.
    const int sidx0 = (2 * wid) * 32 + aidx;
    const int sidx1 = sidx0 + 32;

    // ---- W1 fragments -> paired-kt SMEM layout (once) ----
    for (int i = tid; i < 8192; i += 256) {
        int l   = i & 31;
        int nt  = (i >> 5) & 31;
        int kt2 = i >> 10;
        uint2 lo = WfG[((2 * kt2) * 32 + nt) * 32 + l];
        uint2 hi = WfG[((2 * kt2 + 1) * 32 + nt) * 32 + l];
        uint4 v; v.x = lo.x; v.y = lo.y; v.z = hi.x; v.w = hi.y;
        w1p[i] = v;
    }

    // ---- W2 fragments -> persistent registers (once) ----
    uint2 w2r[16][4];
    {
        const uint2* w2g = WfG + WREC;
#pragma unroll
        for (int kt = 0; kt < 16; kt++)
#pragma unroll
            for (int t = 0; t < 4; t++)
                w2r[kt][t] = w2g[(kt * 32 + nt0 + t) * 32 + lane];
    }

    float bias1[4][2], bias2[4][2];
#pragma unroll
    for (int t = 0; t < 4; t++) {
        int cb = (nt0 + t) * 8 + 2 * c0;
        bias1[t][0] = b1[cb]; bias1[t][1] = b1[cb + 1];
        bias2[t][0] = b2[cb]; bias2[t][1] = b2[cb + 1];
    }

    float zr[4][4], ar[4][4], acc[4][4];
    uint4 bw[4];

    // st[t][d]: d0=(r0,cb) d1=(r0,cb+1) d2=(r0+8,cb) d3=(r0+8,cb+1)
#define STAGE_WRITE(BUF, V)                                                    \
    do {                                                                       \
        uint4 q0, q1;                                                          \
        q0.x = pack2(V[0][0], V[0][1]); q0.y = pack2(V[0][2], V[0][3]);        \
        q0.z = pack2(V[1][0], V[1][1]); q0.w = pack2(V[1][2], V[1][3]);        \
        q1.x = pack2(V[2][0], V[2][1]); q1.y = pack2(V[2][2], V[2][3]);        \
        q1.z = pack2(V[3][0], V[3][1]); q1.w = pack2(V[3][2], V[3][3]);        \
        (BUF)[sidx0] = q0;                                                     \
        (BUF)[sidx1] = q1;                                                     \
    } while (0)

#define PRELOAD_W1()                                                           \
    do {                                                                       \
        _Pragma("unroll")                                                      \
        for (int t = 0; t < 4; t++) bw[t] = w1p[(nt0 + t) * 32 + lane];        \
    } while (0)

    // ---- initial state ----
#pragma unroll
    for (int t = 0; t < 4; t++) {
        int cb = (nt0 + t) * 8 + 2 * c0;
        float2 v0 = *reinterpret_cast<const float2*>(&z0[(row0 + r0) * ZDIM + cb]);
        float2 v1 = *reinterpret_cast<const float2*>(&z0[(row0 + r0 + 8) * ZDIM + cb]);
        zr[t][0] = v0.x; zr[t][1] = v0.y; zr[t][2] = v1.x; zr[t][3] = v1.y;
    }
    STAGE_WRITE(AfU4, zr);
    PRELOAD_W1();
    __syncthreads();

#define FEVAL()                                                                \
    do {                                                                       \
        gemm_w1(AfU4, w1p, bw, lane, nt0, aidx, bias1, acc);                   \
        float hv[4][4];                                                        \
        _Pragma("unroll")                                                      \
        for (int t = 0; t < 4; t++)                                            \
            _Pragma("unroll")                                                  \
            for (int d = 0; d < 4; d++) hv[t][d] = fast_tanh(acc[t][d]);       \
        STAGE_WRITE(HfU4, hv);                                                 \
        __syncthreads();                                                       \
        gemm_w2(HfU4, w2r, aidx, bias2, acc);                                  \
    } while (0)

    for (int s = 0; s < TLEN - 1; s++) {
        const float hs = tg[s + 1] - tg[s];
        const float h6 = hs * (1.0f / 6.0f);
        const float h3 = hs * (1.0f / 3.0f);
        const float h2 = hs * 0.5f;

        // ---- k1 ----
        FEVAL();
        {
            float st[4][4];
#pragma unroll
            for (int t = 0; t < 4; t++)
#pragma unroll
                for (int d = 0; d < 4; d++) {
                    ar[t][d] = fmaf(h6, acc[t][d], zr[t][d]);
                    st[t][d] = fmaf(h2, acc[t][d], zr[t][d]);
                }
            STAGE_WRITE(AfU4, st);
        }
        PRELOAD_W1();
        __syncthreads();

        // ---- k2 ----
        FEVAL();
        {
            float st[4][4];
#pragma unroll
            for (int t = 0; t < 4; t++)
#pragma unroll
                for (int d = 0; d < 4; d++) {
                    ar[t][d] = fmaf(h3, acc[t][d], ar[t][d]);
                    st[t][d] = fmaf(h2, acc[t][d], zr[t][d]);
                }
            STAGE_WRITE(AfU4, st);
        }
        PRELOAD_W1();
        __syncthreads();

        // ---- k3 ----
        FEVAL();
        {
            float st[4][4];
#pragma unroll
            for (int t = 0; t < 4; t++)
#pragma unroll
                for (int d = 0; d < 4; d++) {
                    ar[t][d] = fmaf(h3, acc[t][d], ar[t][d]);
                    st[t][d] = fmaf(hs, acc[t][d], zr[t][d]);
                }
            STAGE_WRITE(AfU4, st);
        }
        PRELOAD_W1();
        __syncthreads();

        // ---- k4 + state update ----
        FEVAL();
#pragma unroll
        for (int t = 0; t < 4; t++)
#pragma unroll
            for (int d = 0; d < 4; d++)
                zr[t][d] = fmaf(h6, acc[t][d], ar[t][d]);
        STAGE_WRITE(AfU4, zr);
        PRELOAD_W1();
        __syncthreads();
    }

#pragma unroll
    for (int t = 0; t < 4; t++) {
        int cb = (nt0 + t) * 8 + 2 * c0;
        float2 v0 = {zr[t][0], zr[t][1]};
        float2 v1 = {zr[t][2], zr[t][3]};
        *reinterpret_cast<float2*>(&out[(row0 + r0) * ZDIM + cb])     = v0;
        *reinterpret_cast<float2*>(&out[(row0 + r0 + 8) * ZDIM + cb]) = v1;
    }
}

extern "C" void kernel_launch(void* const* d_in, const int* in_sizes, int n_in,
                              void* d_out, int out_size)
{
    const float* z0 = (const float*)d_in[0];
    const float* t  = (const float*)d_in[1];
    const float* W1 = (const float*)d_in[2];
    const float* b1 = (const float*)d_in[3];
    const float* W2 = (const float*)d_in[4];
    const float* b2 = (const float*)d_in[5];
    float* out = (float*)d_out;

    cudaFuncSetAttribute(node_kernel,
                         cudaFuncAttributeMaxDynamicSharedMemorySize, SMEM_TOT);

    prep_kernel<<<(2 * WREC + 255) / 256, 256>>>(W1, W2);
    node_kernel<<<NCTA, 256, SMEM_TOT>>>(z0, t, b1, b2, out);
}